// round 1
// baseline (speedup 1.0000x reference)
#include <cuda_runtime.h>
#include <math.h>

// Problem dims
#define BATCH 64
#define SEQLEN 256
#define DMODEL 256
#define DINNER 512
#define DSTATE 16
#define DTRANK 16
#define DCONV 4
#define DIMIN 256
#define DIMOUT 64
#define BL (BATCH * SEQLEN)      // 16384

// Scratch (device globals: no cudaMalloc allowed)
__device__ float g_xin[BL * DINNER];
__device__ float g_z[BL * DINNER];
__device__ float g_xc[BL * DINNER];
__device__ float g_delta[BL * DINNER];
__device__ float g_Bm[BL * DSTATE];
__device__ float g_Cm[BL * DSTATE];
__device__ float g_ybar[BATCH * DINNER];

// ---------------------------------------------------------------------------
// K1: xz = input @ W_in^T ; split into x_in and z
// C[m,n] = sum_k X[m*256+k] * W[n*256+k], M=16384, N=1024, K=256
// Tiled SGEMM: BM=128, BN=64, BK=16, 256 threads, 8x4 micro-tile
// ---------------------------------------------------------------------------
__global__ __launch_bounds__(256) void k1_gemm(const float* __restrict__ X,
                                               const float* __restrict__ W) {
    __shared__ float As[16][136];   // k-major, row stride 136 floats (16B-aligned rows)
    __shared__ float Bs[16][72];

    const int m0 = blockIdx.y * 128;
    const int n0 = blockIdx.x * 64;
    const int tid = threadIdx.x;
    const int tx = tid & 15;        // 16 cols of 4
    const int ty = tid >> 4;        // 16 rows of 8

    float acc[8][4];
#pragma unroll
    for (int i = 0; i < 8; i++)
#pragma unroll
        for (int j = 0; j < 4; j++) acc[i][j] = 0.f;

    for (int k0 = 0; k0 < 256; k0 += 16) {
        // load A tile: 128 rows x 16 k = 2048 elems, 8 per thread
#pragma unroll
        for (int i = 0; i < 8; i++) {
            int e = tid + i * 256;
            int r = e >> 4, kk = e & 15;
            As[kk][r] = X[(m0 + r) * 256 + (k0 + kk)];
        }
        // load B tile: 64 rows x 16 k = 1024 elems, 4 per thread
#pragma unroll
        for (int i = 0; i < 4; i++) {
            int e = tid + i * 256;
            int r = e >> 4, kk = e & 15;
            Bs[kk][r] = W[(n0 + r) * 256 + (k0 + kk)];
        }
        __syncthreads();

#pragma unroll
        for (int kk = 0; kk < 16; kk++) {
            float4 av0 = *reinterpret_cast<const float4*>(&As[kk][ty * 8]);
            float4 av1 = *reinterpret_cast<const float4*>(&As[kk][ty * 8 + 4]);
            float4 bv  = *reinterpret_cast<const float4*>(&Bs[kk][tx * 4]);
            float a[8] = {av0.x, av0.y, av0.z, av0.w, av1.x, av1.y, av1.z, av1.w};
            float b[4] = {bv.x, bv.y, bv.z, bv.w};
#pragma unroll
            for (int i = 0; i < 8; i++)
#pragma unroll
                for (int j = 0; j < 4; j++) acc[i][j] = fmaf(a[i], b[j], acc[i][j]);
        }
        __syncthreads();
    }

#pragma unroll
    for (int i = 0; i < 8; i++) {
        int m = m0 + ty * 8 + i;
#pragma unroll
        for (int j = 0; j < 4; j++) {
            int n = n0 + tx * 4 + j;
            float v = acc[i][j];
            if (n < DINNER) g_xin[m * DINNER + n] = v;
            else            g_z[m * DINNER + (n - DINNER)] = v;
        }
    }
}

// ---------------------------------------------------------------------------
// K2: causal depthwise conv (width 4) + bias + SiLU
// xc[b,l,d] = silu( sum_{j=0..3} x_in[b,l-3+j,d] * conv_w[d,j] + conv_b[d] )
// ---------------------------------------------------------------------------
__global__ __launch_bounds__(256) void k2_conv(const float* __restrict__ cw,
                                               const float* __restrict__ cb) {
    int idx = blockIdx.x * blockDim.x + threadIdx.x;   // over BL*DINNER
    if (idx >= BL * DINNER) return;
    int d = idx % DINNER;
    int l = (idx / DINNER) % SEQLEN;
    int b = idx / (DINNER * SEQLEN);

    float s = cb[d];
#pragma unroll
    for (int j = 0; j < DCONV; j++) {
        int li = l - (DCONV - 1) + j;
        if (li >= 0) s = fmaf(g_xin[(b * SEQLEN + li) * DINNER + d], cw[d * DCONV + j], s);
    }
    // silu
    float sig = 1.f / (1.f + expf(-s));
    g_xc[idx] = s * sig;
}

// ---------------------------------------------------------------------------
// K3: x_dbl = xc @ W_xproj^T (48 outputs); split dt/B/C; delta = softplus(dt@W_dt^T + b_dt)
// 4 (b,l) rows per block to amortize weight traffic. 512 threads.
// ---------------------------------------------------------------------------
__global__ __launch_bounds__(512) void k3_proj(const float* __restrict__ Wx,
                                               const float* __restrict__ Wdt,
                                               const float* __restrict__ bdt) {
    const int bl0 = blockIdx.x * 4;
    __shared__ float sx[4][DINNER];
    __shared__ float sdbl[4][48];
    const int tid = threadIdx.x;

#pragma unroll
    for (int r = 0; r < 4; r++) sx[r][tid] = g_xc[(bl0 + r) * DINNER + tid];
    __syncthreads();

    const int w = tid >> 5, lane = tid & 31;
    for (int o = w; o < 48; o += 16) {
        float s0 = 0.f, s1 = 0.f, s2 = 0.f, s3 = 0.f;
        for (int k = lane; k < DINNER; k += 32) {
            float wv = Wx[o * DINNER + k];
            s0 = fmaf(sx[0][k], wv, s0);
            s1 = fmaf(sx[1][k], wv, s1);
            s2 = fmaf(sx[2][k], wv, s2);
            s3 = fmaf(sx[3][k], wv, s3);
        }
#pragma unroll
        for (int off = 16; off; off >>= 1) {
            s0 += __shfl_down_sync(0xFFFFFFFFu, s0, off);
            s1 += __shfl_down_sync(0xFFFFFFFFu, s1, off);
            s2 += __shfl_down_sync(0xFFFFFFFFu, s2, off);
            s3 += __shfl_down_sync(0xFFFFFFFFu, s3, off);
        }
        if (lane == 0) {
            sdbl[0][o] = s0; sdbl[1][o] = s1; sdbl[2][o] = s2; sdbl[3][o] = s3;
        }
    }
    __syncthreads();

    if (tid < 64) {
        int r = tid >> 4, n = tid & 15;
        g_Bm[(bl0 + r) * DSTATE + n] = sdbl[r][DTRANK + n];
        g_Cm[(bl0 + r) * DSTATE + n] = sdbl[r][DTRANK + DSTATE + n];
    }

    float bv = bdt[tid];
    float wr[DTRANK];
#pragma unroll
    for (int i = 0; i < DTRANK; i++) wr[i] = Wdt[tid * DTRANK + i];
#pragma unroll
    for (int r = 0; r < 4; r++) {
        float acc = bv;
#pragma unroll
        for (int i = 0; i < DTRANK; i++) acc = fmaf(sdbl[r][i], wr[i], acc);
        // softplus, numerically stable
        float sp = fmaxf(acc, 0.f) + log1pf(expf(-fabsf(acc)));
        g_delta[(bl0 + r) * DINNER + tid] = sp;
    }
}

// ---------------------------------------------------------------------------
// K4: selective scan, fused gate + D-skip + mean-pool over L.
// Grid (64, 2): block handles batch b, 256 of the 512 channels.
// Thread = one channel; state h[16] in registers; B/C staged once in smem.
// ---------------------------------------------------------------------------
__global__ __launch_bounds__(256) void k4_scan(const float* __restrict__ A_log,
                                               const float* __restrict__ D_param) {
    const int b = blockIdx.x;
    const int d = blockIdx.y * 256 + threadIdx.x;

    __shared__ float sB[SEQLEN * DSTATE];
    __shared__ float sC[SEQLEN * DSTATE];
    for (int i = threadIdx.x; i < SEQLEN * DSTATE; i += 256) {
        sB[i] = g_Bm[b * SEQLEN * DSTATE + i];
        sC[i] = g_Cm[b * SEQLEN * DSTATE + i];
    }
    __syncthreads();

    float A[DSTATE], h[DSTATE];
#pragma unroll
    for (int n = 0; n < DSTATE; n++) {
        A[n] = -expf(A_log[d * DSTATE + n]);
        h[n] = 0.f;
    }
    const float Dp = D_param[d];

    const float* pdelta = g_delta + (b * SEQLEN) * DINNER + d;
    const float* pxc    = g_xc    + (b * SEQLEN) * DINNER + d;
    const float* pz     = g_z     + (b * SEQLEN) * DINNER + d;

    float ysum = 0.f;
    for (int l = 0; l < SEQLEN; l++) {
        float dt  = pdelta[l * DINNER];
        float xcv = pxc[l * DINNER];
        float zv  = pz[l * DINNER];
        float du  = dt * xcv;
        float y = 0.f;
        const float* Bl = &sB[l * DSTATE];
        const float* Cl = &sC[l * DSTATE];
#pragma unroll
        for (int n = 0; n < DSTATE; n++) {
            float dA = __expf(dt * A[n]);
            h[n] = fmaf(dA, h[n], du * Bl[n]);
            y = fmaf(h[n], Cl[n], y);
        }
        float sig = 1.f / (1.f + expf(-zv));
        ysum = fmaf(fmaf(xcv, Dp, y), zv * sig, ysum);
    }
    g_ybar[b * DINNER + d] = ysum * (1.f / (float)SEQLEN);
}

// ---------------------------------------------------------------------------
// K5: head. e = ybar @ W_out^T ; x = elu(tanh(e @ W_outfc^T + b)) ;
// mu = x @ W_mu^T + b_mu ; sigma = elu(x @ W_sigma^T + b_sigma) + 1 + 1e-14
// One block per batch row, 256 threads.
// ---------------------------------------------------------------------------
__global__ __launch_bounds__(256) void k5_head(const float* __restrict__ W_out,
                                               const float* __restrict__ W_outfc,
                                               const float* __restrict__ b_outfc,
                                               const float* __restrict__ W_mu,
                                               const float* __restrict__ b_mu,
                                               const float* __restrict__ W_sigma,
                                               const float* __restrict__ b_sigma,
                                               float* __restrict__ out) {
    const int b = blockIdx.x;
    const int tid = threadIdx.x;
    __shared__ float sy[DINNER];
    __shared__ float se[DMODEL];
    __shared__ float sxv[DIMIN];

    sy[tid] = g_ybar[b * DINNER + tid];
    sy[tid + 256] = g_ybar[b * DINNER + tid + 256];
    __syncthreads();

    // e[m] = sum_d ybar[d] * W_out[m,d]
    {
        float e = 0.f;
        const float* wr = &W_out[tid * DINNER];
        for (int dd = 0; dd < DINNER; dd++) e = fmaf(sy[dd], wr[dd], e);
        se[tid] = e;
    }
    __syncthreads();

    // x = elu(tanh(e @ W_outfc^T + b_outfc))
    {
        float a = b_outfc[tid];
        const float* wr = &W_outfc[tid * DMODEL];
        for (int k = 0; k < DMODEL; k++) a = fmaf(se[k], wr[k], a);
        float t = tanhf(a);
        float xv = (t > 0.f) ? t : expm1f(t);
        sxv[tid] = xv;
        out[b * DIMIN + tid] = xv;                // x output
    }
    __syncthreads();

    float* out_mu    = out + BATCH * DIMIN;
    float* out_sigma = out + BATCH * DIMIN + BATCH * DIMOUT;
    if (tid < DIMOUT) {
        float a = b_mu[tid];
        const float* wr = &W_mu[tid * DIMIN];
        for (int k = 0; k < DIMIN; k++) a = fmaf(sxv[k], wr[k], a);
        out_mu[b * DIMOUT + tid] = a;
    } else if (tid < 2 * DIMOUT) {
        int o = tid - DIMOUT;
        float a = b_sigma[o];
        const float* wr = &W_sigma[o * DIMIN];
        for (int k = 0; k < DIMIN; k++) a = fmaf(sxv[k], wr[k], a);
        float el = (a > 0.f) ? a : expm1f(a);
        out_sigma[b * DIMOUT + o] = el + 1.f + 1e-14f;
    }
}

// ---------------------------------------------------------------------------
extern "C" void kernel_launch(void* const* d_in, const int* in_sizes, int n_in,
                              void* d_out, int out_size) {
    const float* input   = (const float*)d_in[0];
    const float* W_in    = (const float*)d_in[1];
    const float* conv_w  = (const float*)d_in[2];
    const float* conv_b  = (const float*)d_in[3];
    const float* W_xproj = (const float*)d_in[4];
    const float* W_dt    = (const float*)d_in[5];
    const float* b_dt    = (const float*)d_in[6];
    const float* A_log   = (const float*)d_in[7];
    const float* D_param = (const float*)d_in[8];
    const float* W_out   = (const float*)d_in[9];
    const float* W_outfc = (const float*)d_in[10];
    const float* b_outfc = (const float*)d_in[11];
    const float* W_mu    = (const float*)d_in[12];
    const float* b_mu    = (const float*)d_in[13];
    const float* W_sigma = (const float*)d_in[14];
    const float* b_sigma = (const float*)d_in[15];
    float* out = (float*)d_out;

    k1_gemm<<<dim3(1024 / 64, BL / 128), 256>>>(input, W_in);
    k2_conv<<<(BL * DINNER + 255) / 256, 256>>>(conv_w, conv_b);
    k3_proj<<<BL / 4, 512>>>(W_xproj, W_dt, b_dt);
    k4_scan<<<dim3(BATCH, 2), 256>>>(A_log, D_param);
    k5_head<<<BATCH, 256>>>(W_out, W_outfc, b_outfc, W_mu, b_mu, W_sigma, b_sigma, out);
}

// round 2
// speedup vs baseline: 1.3088x; 1.3088x over previous
#include <cuda_runtime.h>
#include <math.h>

// Problem dims
#define BATCH 64
#define SEQLEN 256
#define DMODEL 256
#define DINNER 512
#define DSTATE 16
#define DTRANK 16
#define DCONV 4
#define DIMIN 256
#define DIMOUT 64
#define BL (BATCH * SEQLEN)      // 16384
#define SEG 4
#define LSEG (SEQLEN / SEG)      // 64

// Scratch (device globals: no cudaMalloc allowed)
__device__ float g_xin[BL * DINNER];
__device__ float g_z[BL * DINNER];
__device__ float g_xc[BL * DINNER];
__device__ float g_delta[BL * DINNER];
__device__ float g_Bm[BL * DSTATE];
__device__ float g_Cm[BL * DSTATE];
__device__ float g_ybar[BATCH * DINNER];
// segment scan partials
__device__ float g_segW[SEG * BATCH * DINNER * DSTATE];
__device__ float g_segP[SEG * BATCH * DINNER * DSTATE];
__device__ float g_segV[SEG * BATCH * DINNER * DSTATE];
__device__ float g_segc[SEG * BATCH * DINNER];

// ---------------------------------------------------------------------------
// K1: xz = input @ W_in^T ; split into x_in and z
// M=16384, N=1024, K=256. BM=BN=128, BK=16, 256 threads, 8x8 micro-tile.
// ---------------------------------------------------------------------------
__global__ __launch_bounds__(256) void k1_gemm(const float* __restrict__ X,
                                               const float* __restrict__ W) {
    __shared__ float As[16][132];   // k-major, padded stride (16B-aligned rows)
    __shared__ float Bs[16][132];

    const int m0 = blockIdx.y * 128;
    const int n0 = blockIdx.x * 128;
    const int tid = threadIdx.x;
    const int tx = tid & 15;
    const int ty = tid >> 4;

    float acc[8][8];
#pragma unroll
    for (int i = 0; i < 8; i++)
#pragma unroll
        for (int j = 0; j < 8; j++) acc[i][j] = 0.f;

    for (int k0 = 0; k0 < 256; k0 += 16) {
#pragma unroll
        for (int i = 0; i < 2; i++) {
            int f = tid + i * 256;          // float4 index 0..511
            int m = f >> 2;                 // 0..127
            int k4 = (f & 3) * 4;           // 0,4,8,12
            float4 va = *reinterpret_cast<const float4*>(&X[(m0 + m) * 256 + k0 + k4]);
            As[k4 + 0][m] = va.x; As[k4 + 1][m] = va.y;
            As[k4 + 2][m] = va.z; As[k4 + 3][m] = va.w;
            float4 vb = *reinterpret_cast<const float4*>(&W[(n0 + m) * 256 + k0 + k4]);
            Bs[k4 + 0][m] = vb.x; Bs[k4 + 1][m] = vb.y;
            Bs[k4 + 2][m] = vb.z; Bs[k4 + 3][m] = vb.w;
        }
        __syncthreads();

#pragma unroll
        for (int kk = 0; kk < 16; kk++) {
            float a[8], b[8];
            *reinterpret_cast<float4*>(&a[0]) = *reinterpret_cast<const float4*>(&As[kk][ty * 8]);
            *reinterpret_cast<float4*>(&a[4]) = *reinterpret_cast<const float4*>(&As[kk][ty * 8 + 4]);
            *reinterpret_cast<float4*>(&b[0]) = *reinterpret_cast<const float4*>(&Bs[kk][tx * 8]);
            *reinterpret_cast<float4*>(&b[4]) = *reinterpret_cast<const float4*>(&Bs[kk][tx * 8 + 4]);
#pragma unroll
            for (int i = 0; i < 8; i++)
#pragma unroll
                for (int j = 0; j < 8; j++) acc[i][j] = fmaf(a[i], b[j], acc[i][j]);
        }
        __syncthreads();
    }

    // whole 128-col tile is entirely in x_in (n0<512) or entirely in z
    float* dstbase = (n0 < DINNER) ? g_xin : g_z;
    const int ncol = (n0 < DINNER) ? (n0 + tx * 8) : (n0 - DINNER + tx * 8);
#pragma unroll
    for (int i = 0; i < 8; i++) {
        int m = m0 + ty * 8 + i;
        float4 o0 = make_float4(acc[i][0], acc[i][1], acc[i][2], acc[i][3]);
        float4 o1 = make_float4(acc[i][4], acc[i][5], acc[i][6], acc[i][7]);
        *reinterpret_cast<float4*>(&dstbase[m * DINNER + ncol]) = o0;
        *reinterpret_cast<float4*>(&dstbase[m * DINNER + ncol + 4]) = o1;
    }
}

// ---------------------------------------------------------------------------
// K2: causal depthwise conv (width 4) + bias + SiLU
// ---------------------------------------------------------------------------
__global__ __launch_bounds__(256) void k2_conv(const float* __restrict__ cw,
                                               const float* __restrict__ cb) {
    int idx = blockIdx.x * blockDim.x + threadIdx.x;
    if (idx >= BL * DINNER) return;
    int d = idx % DINNER;
    int l = (idx / DINNER) % SEQLEN;
    int b = idx / (DINNER * SEQLEN);

    float s = cb[d];
#pragma unroll
    for (int j = 0; j < DCONV; j++) {
        int li = l - (DCONV - 1) + j;
        if (li >= 0) s = fmaf(g_xin[(b * SEQLEN + li) * DINNER + d], cw[d * DCONV + j], s);
    }
    float sig = 1.f / (1.f + expf(-s));
    g_xc[idx] = s * sig;
}

// ---------------------------------------------------------------------------
// K3: x_dbl = xc @ W_xproj^T (48 out); split dt/B/C; delta = softplus(dt@W_dt^T + b_dt)
// 8 (b,l) rows per block, 512 threads.
// ---------------------------------------------------------------------------
#define K3ROWS 8
__global__ __launch_bounds__(512) void k3_proj(const float* __restrict__ Wx,
                                               const float* __restrict__ Wdt,
                                               const float* __restrict__ bdt) {
    const int bl0 = blockIdx.x * K3ROWS;
    __shared__ float sx[K3ROWS][DINNER];
    __shared__ float sdbl[K3ROWS][48];
    const int tid = threadIdx.x;

#pragma unroll
    for (int r = 0; r < K3ROWS; r++) sx[r][tid] = g_xc[(bl0 + r) * DINNER + tid];
    __syncthreads();

    const int w = tid >> 5, lane = tid & 31;
    for (int o = w; o < 48; o += 16) {
        float s[K3ROWS];
#pragma unroll
        for (int r = 0; r < K3ROWS; r++) s[r] = 0.f;
        for (int k = lane; k < DINNER; k += 32) {
            float wv = Wx[o * DINNER + k];
#pragma unroll
            for (int r = 0; r < K3ROWS; r++) s[r] = fmaf(sx[r][k], wv, s[r]);
        }
#pragma unroll
        for (int off = 16; off; off >>= 1)
#pragma unroll
            for (int r = 0; r < K3ROWS; r++) s[r] += __shfl_down_sync(0xFFFFFFFFu, s[r], off);
        if (lane == 0) {
#pragma unroll
            for (int r = 0; r < K3ROWS; r++) sdbl[r][o] = s[r];
        }
    }
    __syncthreads();

    // write B and C: 8 rows x 16 each
    if (tid < K3ROWS * 16) {
        int r = tid >> 4, n = tid & 15;
        g_Bm[(bl0 + r) * DSTATE + n] = sdbl[r][DTRANK + n];
    } else if (tid < 2 * K3ROWS * 16) {
        int t = tid - K3ROWS * 16;
        int r = t >> 4, n = t & 15;
        g_Cm[(bl0 + r) * DSTATE + n] = sdbl[r][DTRANK + DSTATE + n];
    }

    float bv = bdt[tid];
    float wr[DTRANK];
#pragma unroll
    for (int i = 0; i < DTRANK; i++) wr[i] = Wdt[tid * DTRANK + i];
#pragma unroll
    for (int r = 0; r < K3ROWS; r++) {
        float acc = bv;
#pragma unroll
        for (int i = 0; i < DTRANK; i++) acc = fmaf(sdbl[r][i], wr[i], acc);
        float sp = fmaxf(acc, 0.f) + log1pf(expf(-fabsf(acc)));
        g_delta[(bl0 + r) * DINNER + tid] = sp;
    }
}

// ---------------------------------------------------------------------------
// K4a: segmented selective scan. Grid (64, 4, SEG), 128 threads.
// Each thread: channel d, batch b, segment s over LSEG steps.
// Emits per segment: P_end[16] (decay product), v_end[16] (state from h_in=0),
// W[16] = sum_l gate_l * C_l * Pprefix_l, c = sum_l gate_l*(C.v_l + xc*Dp)
// ---------------------------------------------------------------------------
template <bool FAST>
__device__ __forceinline__ void seg_scan_body(
    int b, int d, int s, const float* __restrict__ A,
    float Dp, const float* __restrict__ sB, const float* __restrict__ sC)
{
    float P[DSTATE], V[DSTATE], Wc[DSTATE];
#pragma unroll
    for (int n = 0; n < DSTATE; n++) { P[n] = 1.f; V[n] = 0.f; Wc[n] = 0.f; }
    float c = 0.f;
    const float A0 = A[0];

    const int l0 = s * LSEG;
    const float* pdelta = g_delta + ((size_t)(b * SEQLEN + l0)) * DINNER + d;
    const float* pxc    = g_xc    + ((size_t)(b * SEQLEN + l0)) * DINNER + d;
    const float* pz     = g_z     + ((size_t)(b * SEQLEN + l0)) * DINNER + d;

    for (int l = 0; l < LSEG; l++) {
        float dt  = pdelta[l * DINNER];
        float xcv = pxc[l * DINNER];
        float zv  = pz[l * DINNER];
        float gate = __fdividef(zv, 1.f + __expf(-zv));   // z * sigmoid(z)
        float du = dt * xcv;
        float yl = 0.f;
        float p = 1.f, r = 0.f;
        if (FAST) r = __expf(dt * A0);
#pragma unroll
        for (int n = 0; n < DSTATE; n++) {
            float dA;
            if (FAST) { p *= r; dA = p; }
            else      { dA = __expf(dt * A[n]); }
            float Bn = sB[l * DSTATE + n];
            float Cn = sC[l * DSTATE + n];
            P[n] *= dA;
            V[n] = fmaf(dA, V[n], du * Bn);
            yl = fmaf(V[n], Cn, yl);
            Wc[n] = fmaf(gate * Cn, P[n], Wc[n]);
        }
        c = fmaf(gate, fmaf(xcv, Dp, yl), c);
    }

    size_t base = (((size_t)s * BATCH + b) * DINNER + d) * DSTATE;
#pragma unroll
    for (int q = 0; q < DSTATE; q += 4) {
        *reinterpret_cast<float4*>(&g_segP[base + q]) = make_float4(P[q], P[q+1], P[q+2], P[q+3]);
        *reinterpret_cast<float4*>(&g_segV[base + q]) = make_float4(V[q], V[q+1], V[q+2], V[q+3]);
        *reinterpret_cast<float4*>(&g_segW[base + q]) = make_float4(Wc[q], Wc[q+1], Wc[q+2], Wc[q+3]);
    }
    g_segc[((size_t)s * BATCH + b) * DINNER + d] = c;
}

__global__ __launch_bounds__(128) void k4_seg(const float* __restrict__ A_log,
                                              const float* __restrict__ D_param) {
    const int b = blockIdx.x;
    const int d = blockIdx.y * 128 + threadIdx.x;
    const int s = blockIdx.z;

    __shared__ float sB[LSEG * DSTATE];
    __shared__ float sC[LSEG * DSTATE];
    {
        const float* gB = g_Bm + ((size_t)b * SEQLEN + s * LSEG) * DSTATE;
        const float* gC = g_Cm + ((size_t)b * SEQLEN + s * LSEG) * DSTATE;
        for (int i = threadIdx.x * 4; i < LSEG * DSTATE; i += 128 * 4) {
            *reinterpret_cast<float4*>(&sB[i]) = *reinterpret_cast<const float4*>(&gB[i]);
            *reinterpret_cast<float4*>(&sC[i]) = *reinterpret_cast<const float4*>(&gC[i]);
        }
    }
    __syncthreads();

    float A[DSTATE];
    bool fast = true;
#pragma unroll
    for (int n = 0; n < DSTATE; n++) {
        A[n] = -expf(A_log[d * DSTATE + n]);
        // fast path valid iff A[n] == (n+1)*A[0] (to fp tolerance)
        fast = fast && (fabsf(A[n] - (float)(n + 1) * A[0]) <= 1e-4f * fabsf(A[n]));
    }
    const float Dp = D_param[d];

    if (fast) seg_scan_body<true >(b, d, s, A, Dp, sB, sC);
    else      seg_scan_body<false>(b, d, s, A, Dp, sB, sC);
}

// K4b: combine segments. Grid (64,4), 128 threads.
__global__ __launch_bounds__(128) void k4_combine() {
    const int b = blockIdx.x;
    const int d = blockIdx.y * 128 + threadIdx.x;

    float h[DSTATE];
#pragma unroll
    for (int n = 0; n < DSTATE; n++) h[n] = 0.f;
    float ysum = 0.f;

#pragma unroll
    for (int s = 0; s < SEG; s++) {
        size_t base = (((size_t)s * BATCH + b) * DINNER + d) * DSTATE;
        float dot = g_segc[((size_t)s * BATCH + b) * DINNER + d];
#pragma unroll
        for (int q = 0; q < DSTATE; q += 4) {
            float4 Wv = *reinterpret_cast<const float4*>(&g_segW[base + q]);
            float4 Pv = *reinterpret_cast<const float4*>(&g_segP[base + q]);
            float4 Vv = *reinterpret_cast<const float4*>(&g_segV[base + q]);
            dot = fmaf(Wv.x, h[q+0], dot);
            dot = fmaf(Wv.y, h[q+1], dot);
            dot = fmaf(Wv.z, h[q+2], dot);
            dot = fmaf(Wv.w, h[q+3], dot);
            h[q+0] = fmaf(Pv.x, h[q+0], Vv.x);
            h[q+1] = fmaf(Pv.y, h[q+1], Vv.y);
            h[q+2] = fmaf(Pv.z, h[q+2], Vv.z);
            h[q+3] = fmaf(Pv.w, h[q+3], Vv.w);
        }
        ysum += dot;
    }
    g_ybar[(size_t)b * DINNER + d] = ysum * (1.f / (float)SEQLEN);
}

// ---------------------------------------------------------------------------
// K5: head
// ---------------------------------------------------------------------------
__global__ __launch_bounds__(256) void k5_head(const float* __restrict__ W_out,
                                               const float* __restrict__ W_outfc,
                                               const float* __restrict__ b_outfc,
                                               const float* __restrict__ W_mu,
                                               const float* __restrict__ b_mu,
                                               const float* __restrict__ W_sigma,
                                               const float* __restrict__ b_sigma,
                                               float* __restrict__ out) {
    const int b = blockIdx.x;
    const int tid = threadIdx.x;
    __shared__ float sy[DINNER];
    __shared__ float se[DMODEL];
    __shared__ float sxv[DIMIN];

    sy[tid] = g_ybar[b * DINNER + tid];
    sy[tid + 256] = g_ybar[b * DINNER + tid + 256];
    __syncthreads();

    {
        float e = 0.f;
        const float* wr = &W_out[tid * DINNER];
        for (int dd = 0; dd < DINNER; dd++) e = fmaf(sy[dd], wr[dd], e);
        se[tid] = e;
    }
    __syncthreads();

    {
        float a = b_outfc[tid];
        const float* wr = &W_outfc[tid * DMODEL];
        for (int k = 0; k < DMODEL; k++) a = fmaf(se[k], wr[k], a);
        float t = tanhf(a);
        float xv = (t > 0.f) ? t : expm1f(t);
        sxv[tid] = xv;
        out[b * DIMIN + tid] = xv;
    }
    __syncthreads();

    float* out_mu    = out + BATCH * DIMIN;
    float* out_sigma = out + BATCH * DIMIN + BATCH * DIMOUT;
    if (tid < DIMOUT) {
        float a = b_mu[tid];
        const float* wr = &W_mu[tid * DIMIN];
        for (int k = 0; k < DIMIN; k++) a = fmaf(sxv[k], wr[k], a);
        out_mu[b * DIMOUT + tid] = a;
    } else if (tid < 2 * DIMOUT) {
        int o = tid - DIMOUT;
        float a = b_sigma[o];
        const float* wr = &W_sigma[o * DIMIN];
        for (int k = 0; k < DIMIN; k++) a = fmaf(sxv[k], wr[k], a);
        float el = (a > 0.f) ? a : expm1f(a);
        out_sigma[b * DIMOUT + o] = el + 1.f + 1e-14f;
    }
}

// ---------------------------------------------------------------------------
extern "C" void kernel_launch(void* const* d_in, const int* in_sizes, int n_in,
                              void* d_out, int out_size) {
    const float* input   = (const float*)d_in[0];
    const float* W_in    = (const float*)d_in[1];
    const float* conv_w  = (const float*)d_in[2];
    const float* conv_b  = (const float*)d_in[3];
    const float* W_xproj = (const float*)d_in[4];
    const float* W_dt    = (const float*)d_in[5];
    const float* b_dt    = (const float*)d_in[6];
    const float* A_log   = (const float*)d_in[7];
    const float* D_param = (const float*)d_in[8];
    const float* W_out   = (const float*)d_in[9];
    const float* W_outfc = (const float*)d_in[10];
    const float* b_outfc = (const float*)d_in[11];
    const float* W_mu    = (const float*)d_in[12];
    const float* b_mu    = (const float*)d_in[13];
    const float* W_sigma = (const float*)d_in[14];
    const float* b_sigma = (const float*)d_in[15];
    float* out = (float*)d_out;

    k1_gemm<<<dim3(1024 / 128, BL / 128), 256>>>(input, W_in);
    k2_conv<<<(BL * DINNER + 255) / 256, 256>>>(conv_w, conv_b);
    k3_proj<<<BL / K3ROWS, 512>>>(W_xproj, W_dt, b_dt);
    k4_seg<<<dim3(BATCH, DINNER / 128, SEG), 128>>>(A_log, D_param);
    k4_combine<<<dim3(BATCH, DINNER / 128), 128>>>();
    k5_head<<<BATCH, 256>>>(W_out, W_outfc, b_outfc, W_mu, b_mu, W_sigma, b_sigma, out);
}